// round 5
// baseline (speedup 1.0000x reference)
#include <cuda_runtime.h>
#include <math.h>

// B=4, T=1024, C=2048, NH=16, HS=128, NLQ=512, NLKV=512, DHR=64
// scale = 1/sqrt(192)

// ---------------- scratch (device globals) ------------------------------------
__device__ float g_keff[16L * 512 * 512];        //  16 MB
__device__ float g_M[512L * 2048];               //   4 MB
__device__ float g_wcat[640L * 2048];            //   5 MB  [W_dq ; W_kr ; pad] (tf32)
__device__ float g_xr[4096L * 2048];             //  32 MB  x rounded to tf32
__device__ float g_wdkv[512L * 2048];            //   4 MB
__device__ float g_wqr[1024L * 512];             //   2 MB
__device__ float g_wuq[2048L * 512];             //   4 MB
__device__ float g_wuk[2048L * 512];             //   4 MB
__device__ float g_wuv[2048L * 512];             //   4 MB
__device__ float g_wo[2048L * 2048];             //  16 MB
__device__ float g_cqx[4096L * 640];             //  10 MB  [c_q | c_kr | pad]
__device__ float g_cqr[4096L * 1024];            //  16 MB
__device__ float g_qcat[64L * 1024 * 576];       // 151 MB  [q_abs | q_r]; reused for y_c
__device__ float g_kcat[4096L * 576];            // 9.4 MB  [c_kv | k_r]
__device__ float g_logits[64L * 1024 * 1024];    // 256 MB  logits -> P (in place)

// ---------------- helpers -------------------------------------------------------
__device__ __forceinline__ unsigned f2tf(float f) {
    unsigned u;
    asm("cvt.rna.tf32.f32 %0, %1;" : "=r"(u) : "f"(f));
    return u;
}
__device__ __forceinline__ float f2tff(float f) { return __uint_as_float(f2tf(f)); }

__device__ __forceinline__ void mma_tf32(float* c, const unsigned* a, const unsigned* b) {
    asm volatile(
        "mma.sync.aligned.m16n8k8.row.col.f32.tf32.tf32.f32 "
        "{%0,%1,%2,%3}, {%4,%5,%6,%7}, {%8,%9}, {%0,%1,%2,%3};"
        : "+f"(c[0]), "+f"(c[1]), "+f"(c[2]), "+f"(c[3])
        : "r"(a[0]), "r"(a[1]), "r"(a[2]), "r"(a[3]), "r"(b[0]), "r"(b[1]));
}

#define CP16(dst, src) \
    asm volatile("cp.async.cg.shared.global [%0], [%1], 16;" :: "r"(dst), "l"(src))
#define CP_COMMIT() asm volatile("cp.async.commit_group;")
#define CP_WAIT1()  asm volatile("cp.async.wait_group 1;")

// ---------------- tf32 GEMM v4: cp.async 3-stage, 256 threads, 64x64 warp tiles --
// Block tile 256(M) x 128(N) x 32(K). 8 warps as 4(m) x 2(n), warp tile 64x64.
// Operands must already be tf32-rounded fp32 bit patterns.
// Smem layouts (words):
//   TA=0: As[m][k]  stride 36   TA=1: As[k][m]  stride 264
//   TB=1: Bs[n][k]  stride 36   TB=0: Bs[k][n]  stride 136
// MODE: 0 plain, 1 causal tile-skip, 2 causal K-limit. ROUND: tf32-round output.
#define ASZW 9216            // A stage words (256*36)
#define BSZW 4608            // max B stage words (128*36)
#define STAGEW (ASZW + BSZW) // 13824 words
#define SMEM_BYTES (3 * STAGEW * 4)  // 165888 B

template <bool TA, bool TB, int MODE, bool ROUND>
__global__ void __launch_bounds__(256, 1) gemm_tc4(
        const float* __restrict__ A, const float* __restrict__ B,
        float* __restrict__ C, int M, int N, int K,
        int lda, int ldb, int ldc,
        long long sAq, long long sAr, long long sBq, long long sBr,
        long long sCq, long long sCr, int zdiv) {
    const int m0 = blockIdx.y * 256;
    const int n0 = blockIdx.x * 128;
    if (MODE == 1 && n0 >= m0 + 256) return;

    int z = blockIdx.z;
    int zq = z / zdiv, zr = z % zdiv;
    A += (long long)zq * sAq + (long long)zr * sAr;
    B += (long long)zq * sBq + (long long)zr * sBr;
    C += (long long)zq * sCq + (long long)zr * sCr;

    const int Keff = (MODE == 2) ? ((m0 + 256 < K) ? m0 + 256 : K) : K;
    const int ntiles = Keff >> 5;

    extern __shared__ float sh[];
    const unsigned shb = (unsigned)__cvta_generic_to_shared(sh);

    const int tid  = threadIdx.x;
    const int lane = tid & 31;
    const int warp = tid >> 5;
    const int wm = (warp >> 1) * 64;   // 0,64,128,192
    const int wn = (warp & 1) * 64;    // 0,64
    const int lane4 = lane & 3;
    const int laneg = lane >> 2;

    float acc[4][8][4] = {};

    auto issue = [&](int t) {
        const int k0 = t << 5;
        const unsigned As = shb + (t % 3) * (STAGEW * 4);
        const unsigned Bs = As + ASZW * 4;
        if (!TA) {
            // A rows: one row of 32 floats per thread (8 CP16)
            const float* src = A + (long long)(m0 + tid) * lda + k0;
            const unsigned dst = As + tid * 36 * 4;
#pragma unroll
            for (int i = 0; i < 8; i++) CP16(dst + i * 16, src + i * 4);
        } else {
            const int k = tid >> 3, f = (tid & 7) * 32;
            const float* src = A + (long long)(k0 + k) * lda + m0 + f;
            const unsigned dst = As + (k * 264 + f) * 4;
#pragma unroll
            for (int i = 0; i < 8; i++) CP16(dst + i * 16, src + i * 4);
        }
        if (TB) {
            const int n = tid >> 1, f = (tid & 1) * 16;
            const float* src = B + (long long)(n0 + n) * ldb + k0 + f;
            const unsigned dst = Bs + (n * 36 + f) * 4;
#pragma unroll
            for (int i = 0; i < 4; i++) CP16(dst + i * 16, src + i * 4);
        } else {
            const int k = tid >> 3, f = (tid & 7) * 16;
            const float* src = B + (long long)(k0 + k) * ldb + n0 + f;
            const unsigned dst = Bs + (k * 136 + f) * 4;
#pragma unroll
            for (int i = 0; i < 4; i++) CP16(dst + i * 16, src + i * 4);
        }
        CP_COMMIT();
    };

    issue(0);
    if (ntiles > 1) issue(1);

    for (int t = 0; t < ntiles; t++) {
        CP_WAIT1();
        __syncthreads();
        if (t + 2 < ntiles) issue(t + 2);

        const unsigned* As = (const unsigned*)sh + (t % 3) * STAGEW;
        const unsigned* Bs = As + ASZW;

#pragma unroll
        for (int kk = 0; kk < 32; kk += 8) {
            const int k1 = kk + lane4, k2 = k1 + 4;
            unsigned a[4][4], b[8][2];
#pragma unroll
            for (int mi = 0; mi < 4; mi++) {
                const int mr = wm + mi * 16 + laneg;
                if (!TA) {
                    a[mi][0] = As[mr * 36 + k1];
                    a[mi][1] = As[(mr + 8) * 36 + k1];
                    a[mi][2] = As[mr * 36 + k2];
                    a[mi][3] = As[(mr + 8) * 36 + k2];
                } else {
                    a[mi][0] = As[k1 * 264 + mr];
                    a[mi][1] = As[k1 * 264 + mr + 8];
                    a[mi][2] = As[k2 * 264 + mr];
                    a[mi][3] = As[k2 * 264 + mr + 8];
                }
            }
#pragma unroll
            for (int ni = 0; ni < 8; ni++) {
                const int nc = wn + ni * 8 + laneg;
                if (TB) {
                    b[ni][0] = Bs[nc * 36 + k1];
                    b[ni][1] = Bs[nc * 36 + k2];
                } else {
                    b[ni][0] = Bs[k1 * 136 + nc];
                    b[ni][1] = Bs[k2 * 136 + nc];
                }
            }
#pragma unroll
            for (int mi = 0; mi < 4; mi++)
#pragma unroll
                for (int ni = 0; ni < 8; ni++)
                    mma_tf32(acc[mi][ni], a[mi], b[ni]);
        }
        __syncthreads();
    }

#pragma unroll
    for (int mi = 0; mi < 4; mi++) {
#pragma unroll
        for (int ni = 0; ni < 8; ni++) {
            const int row = m0 + wm + mi * 16 + laneg;
            const int col = n0 + wn + ni * 8 + lane4 * 2;
            float v0 = acc[mi][ni][0], v1 = acc[mi][ni][1];
            float v2 = acc[mi][ni][2], v3 = acc[mi][ni][3];
            if (ROUND) { v0 = f2tff(v0); v1 = f2tff(v1); v2 = f2tff(v2); v3 = f2tff(v3); }
            *reinterpret_cast<float2*>(&C[(long long)row * ldc + col]) = make_float2(v0, v1);
            *reinterpret_cast<float2*>(&C[(long long)(row + 8) * ldc + col]) = make_float2(v2, v3);
        }
    }
}

// ---------------- tf32 round-copy ----------------------------------------------
__global__ void round_copy(const float* __restrict__ in, float* __restrict__ out, int n4) {
    int idx = blockIdx.x * blockDim.x + threadIdx.x;
    if (idx >= n4) return;
    float4 v = reinterpret_cast<const float4*>(in)[idx];
    v.x = f2tff(v.x); v.y = f2tff(v.y); v.z = f2tff(v.z); v.w = f2tff(v.w);
    reinterpret_cast<float4*>(out)[idx] = v;
}

// ---------------- weight concat: Wcat = [W_dq ; W_kr ; pad] (rounded) -----------
__global__ void build_wcat(const float* __restrict__ Wdq,
                           const float* __restrict__ Wkr,
                           float* __restrict__ Wcat) {
    int idx = blockIdx.x * blockDim.x + threadIdx.x;
    if (idx >= 576 * 512) return;
    int row = idx >> 9, c4 = idx & 511;
    float4 v = (row < 512)
        ? reinterpret_cast<const float4*>(Wdq)[row * 512 + c4]
        : reinterpret_cast<const float4*>(Wkr)[(row - 512) * 512 + c4];
    v.x = f2tff(v.x); v.y = f2tff(v.y); v.z = f2tff(v.z); v.w = f2tff(v.w);
    reinterpret_cast<float4*>(Wcat)[row * 512 + c4] = v;
}

// ---------------- rope (tf32-rounded outputs) -----------------------------------
__global__ void rope_q_kernel(const float* __restrict__ cqr,
                              const float* __restrict__ fc,
                              const float* __restrict__ fs,
                              float* __restrict__ qcat) {
    int idx = blockIdx.x * blockDim.x + threadIdx.x;
    if (idx >= 4 * 1024 * 16 * 32) return;
    int j = idx & 31;
    int h = (idx >> 5) & 15;
    int t = (idx >> 9) & 1023;
    int b = idx >> 19;
    long long src = (((long long)(b * 1024 + t)) * 1024) + h * 64 + 2 * j;
    float re = cqr[src], im = cqr[src + 1];
    float c = fc[t * 32 + j], s = fs[t * 32 + j];
    long long dst = (((long long)(b * 16 + h)) * 1024 + t) * 576 + 512 + 2 * j;
    qcat[dst]     = f2tff(re * c - im * s);
    qcat[dst + 1] = f2tff(re * s + im * c);
}

__global__ void rope_k_kernel(const float* __restrict__ cqx,
                              const float* __restrict__ fc,
                              const float* __restrict__ fs,
                              float* __restrict__ kcat) {
    int idx = blockIdx.x * blockDim.x + threadIdx.x;
    if (idx >= 4 * 1024 * 32) return;
    int j = idx & 31;
    int t = (idx >> 5) & 1023;
    int b = idx >> 15;
    long long src = ((long long)(b * 1024 + t)) * 640 + 512 + 2 * j;
    float re = cqx[src], im = cqx[src + 1];
    float c = fc[t * 32 + j], s = fs[t * 32 + j];
    long long dst = ((long long)(b * 1024 + t)) * 576 + 512 + 2 * j;
    kcat[dst]     = f2tff(re * c - im * s);
    kcat[dst + 1] = f2tff(re * s + im * c);
}

// ---------------- softmax (in place, tf32-rounded P) ----------------------------
__global__ void softmax_kernel(float* __restrict__ L) {
    const int r = blockIdx.x;
    const int t = r & 1023;
    float* row = L + (long long)r * 1024;
    const float scale = 0.07216878364870323f;
    const int tid = threadIdx.x;  // 128
    __shared__ float red[128];

    float m = -INFINITY;
    for (int s = tid; s <= t; s += 128) m = fmaxf(m, row[s]);
    red[tid] = m;
    __syncthreads();
    for (int o = 64; o; o >>= 1) {
        if (tid < o) red[tid] = fmaxf(red[tid], red[tid + o]);
        __syncthreads();
    }
    m = red[0] * scale;
    __syncthreads();

    float sum = 0.0f;
    for (int s = tid; s <= t; s += 128) sum += __expf(row[s] * scale - m);
    red[tid] = sum;
    __syncthreads();
    for (int o = 64; o; o >>= 1) {
        if (tid < o) red[tid] += red[tid + o];
        __syncthreads();
    }
    float inv = 1.0f / red[0];
    __syncthreads();

    for (int s = tid; s < 1024; s += 128)
        row[s] = (s <= t) ? f2tff(__expf(row[s] * scale - m) * inv) : 0.0f;
}

// ---------------- launcher -------------------------------------------------------
extern "C" void kernel_launch(void* const* d_in, const int* in_sizes, int n_in,
                              void* d_out, int out_size) {
    (void)in_sizes; (void)n_in; (void)out_size;
    const float* x     = (const float*)d_in[0];
    const float* W_dq  = (const float*)d_in[1];
    const float* W_uq  = (const float*)d_in[2];
    const float* W_dkv = (const float*)d_in[3];
    const float* W_uk  = (const float*)d_in[4];
    const float* W_uv  = (const float*)d_in[5];
    const float* W_o   = (const float*)d_in[6];
    const float* W_qr  = (const float*)d_in[7];
    const float* W_kr  = (const float*)d_in[8];
    const float* fc    = (const float*)d_in[9];
    const float* fs    = (const float*)d_in[10];
    float* out = (float*)d_out;

    float *keff, *Mm, *wcat, *xr, *wdkv, *wqr, *wuq, *wuk, *wuv, *wo;
    float *cqx, *cqr, *qcat, *kcat, *logits;
    cudaGetSymbolAddress((void**)&keff,   g_keff);
    cudaGetSymbolAddress((void**)&Mm,     g_M);
    cudaGetSymbolAddress((void**)&wcat,   g_wcat);
    cudaGetSymbolAddress((void**)&xr,     g_xr);
    cudaGetSymbolAddress((void**)&wdkv,   g_wdkv);
    cudaGetSymbolAddress((void**)&wqr,    g_wqr);
    cudaGetSymbolAddress((void**)&wuq,    g_wuq);
    cudaGetSymbolAddress((void**)&wuk,    g_wuk);
    cudaGetSymbolAddress((void**)&wuv,    g_wuv);
    cudaGetSymbolAddress((void**)&wo,     g_wo);
    cudaGetSymbolAddress((void**)&cqx,    g_cqx);
    cudaGetSymbolAddress((void**)&cqr,    g_cqr);
    cudaGetSymbolAddress((void**)&qcat,   g_qcat);
    cudaGetSymbolAddress((void**)&kcat,   g_kcat);
    cudaGetSymbolAddress((void**)&logits, g_logits);

    cudaFuncSetAttribute(gemm_tc4<false, true,  0, true >, cudaFuncAttributeMaxDynamicSharedMemorySize, SMEM_BYTES);
    cudaFuncSetAttribute(gemm_tc4<false, false, 0, true >, cudaFuncAttributeMaxDynamicSharedMemorySize, SMEM_BYTES);
    cudaFuncSetAttribute(gemm_tc4<true,  true,  0, true >, cudaFuncAttributeMaxDynamicSharedMemorySize, SMEM_BYTES);
    cudaFuncSetAttribute(gemm_tc4<false, true,  0, false>, cudaFuncAttributeMaxDynamicSharedMemorySize, SMEM_BYTES);
    cudaFuncSetAttribute(gemm_tc4<false, true,  1, false>, cudaFuncAttributeMaxDynamicSharedMemorySize, SMEM_BYTES);
    cudaFuncSetAttribute(gemm_tc4<false, false, 2, true >, cudaFuncAttributeMaxDynamicSharedMemorySize, SMEM_BYTES);
    cudaFuncSetAttribute(gemm_tc4<false, false, 0, false>, cudaFuncAttributeMaxDynamicSharedMemorySize, SMEM_BYTES);

    dim3 blk(256);
    const long long QZ = 1024LL * 576;
    const long long KZ = 1024LL * 576;
    const long long LZ = 1024LL * 1024;
    const long long YZ = 1024LL * 512;

    // --- pre-round operands to tf32 ---
    round_copy<<<(2097152 + 255) / 256, 256>>>(x,     xr,   2097152);
    round_copy<<<(262144  + 255) / 256, 256>>>(W_dkv, wdkv, 262144);
    round_copy<<<(131072  + 255) / 256, 256>>>(W_qr,  wqr,  131072);
    round_copy<<<(262144  + 255) / 256, 256>>>(W_uq,  wuq,  262144);
    round_copy<<<(262144  + 255) / 256, 256>>>(W_uk,  wuk,  262144);
    round_copy<<<(262144  + 255) / 256, 256>>>(W_uv,  wuv,  262144);
    round_copy<<<(1048576 + 255) / 256, 256>>>(W_o,   wo,   1048576);
    build_wcat<<<(576 * 512 + 255) / 256, 256>>>(W_dq, W_kr, wcat);

    // 1) cqx (4096x640) = x @ Wcat^T
    gemm_tc4<false, true, 0, true><<<dim3(5, 16, 1), blk, SMEM_BYTES>>>(
        xr, wcat, cqx, 4096, 640, 2048, 2048, 2048, 640,
        0, 0, 0, 0, 0, 0, 1);

    // 2) kcat[:, 0:512] = x @ W_dkv^T
    gemm_tc4<false, true, 0, true><<<dim3(4, 16, 1), blk, SMEM_BYTES>>>(
        xr, wdkv, kcat, 4096, 512, 2048, 2048, 2048, 576,
        0, 0, 0, 0, 0, 0, 1);

    // 3) k_eff[h] = Wuq_slice @ Wuk_slice
    gemm_tc4<false, false, 0, true><<<dim3(4, 2, 16), blk, SMEM_BYTES>>>(
        wuq, wuk, keff, 512, 512, 128, 2048, 512, 512,
        128, 0, 128LL * 512, 0, 512LL * 512, 0, 1);

    // 4) M = W_uv^T @ W_o^T
    gemm_tc4<true, true, 0, true><<<dim3(16, 2, 1), blk, SMEM_BYTES>>>(
        wuv, wo, Mm, 512, 2048, 2048, 512, 2048, 2048,
        0, 0, 0, 0, 0, 0, 1);

    // 5) c_qr = c_q @ W_qr^T   (no round; rope rounds)
    gemm_tc4<false, true, 0, false><<<dim3(8, 16, 1), blk, SMEM_BYTES>>>(
        cqx, wqr, cqr, 4096, 1024, 512, 640, 512, 1024,
        0, 0, 0, 0, 0, 0, 1);

    // 6) rope into concat tails
    rope_q_kernel<<<8192, 256>>>(cqr, fc, fs, qcat);
    rope_k_kernel<<<512, 256>>>(cqx, fc, fs, kcat);

    // 7) q_abs -> qcat[:, 0:512] = c_q[b] @ k_eff[h]
    gemm_tc4<false, false, 0, true><<<dim3(4, 4, 64), blk, SMEM_BYTES>>>(
        cqx, keff, qcat, 1024, 512, 512, 640, 512, 576,
        1024LL * 640, 0, 0, 512LL * 512,
        16LL * QZ, QZ, 16);

    // 8) logits = qcat @ kcat^T (K=576), causal tile-skip
    gemm_tc4<false, true, 1, false><<<dim3(8, 4, 64), blk, SMEM_BYTES>>>(
        qcat, kcat, logits, 1024, 1024, 576, 576, 576, 1024,
        16LL * QZ, QZ, KZ, 0,
        16LL * LZ, LZ, 16);

    // 9) softmax
    softmax_kernel<<<65536, 128>>>(logits);

    // 10) y_c = P @ c_kv, causal K-limit
    gemm_tc4<false, false, 2, true><<<dim3(4, 4, 64), blk, SMEM_BYTES>>>(
        logits, kcat, qcat, 1024, 512, 1024, 1024, 576, 512,
        16LL * LZ, LZ, KZ, 0,
        16LL * YZ, YZ, 16);

    // 11) out = y_c @ M slices
    gemm_tc4<false, false, 0, false><<<dim3(1, 4, 64), blk, SMEM_BYTES>>>(
        qcat, Mm, out, 1024, 128, 512, 512, 2048, 2048,
        16LL * YZ, YZ, 0, 128,
        1024LL * 2048, 128, 16);
}

// round 6
// speedup vs baseline: 1.2755x; 1.2755x over previous
#include <cuda_runtime.h>
#include <math.h>

// B=4, T=1024, C=2048, NH=16, HS=128, NLQ=512, NLKV=512, DHR=64
// scale = 1/sqrt(192)

// ---------------- scratch (device globals) ------------------------------------
__device__ float g_keff[16L * 512 * 512];        //  16 MB
__device__ float g_M[512L * 2048];               //   4 MB
__device__ float g_wcat[640L * 2048];            //   5 MB  [W_dq ; W_kr ; pad] (tf32)
__device__ float g_xr[4096L * 2048];             //  32 MB  x rounded to tf32
__device__ float g_wdkv[512L * 2048];            //   4 MB
__device__ float g_wqr[1024L * 512];             //   2 MB
__device__ float g_wuq[2048L * 512];             //   4 MB
__device__ float g_wuk[2048L * 512];             //   4 MB
__device__ float g_wuv[2048L * 512];             //   4 MB
__device__ float g_wo[2048L * 2048];             //  16 MB
__device__ float g_cqx[4096L * 640];             //  10 MB  [c_q | c_kr | pad]
__device__ float g_cqr[4096L * 1024];            //  16 MB
__device__ float g_qcat[64L * 1024 * 576];       // 151 MB  [q_abs | q_r]
__device__ float g_kcat[4096L * 576];            // 9.4 MB  [c_kv | k_r]
__device__ float g_v[64L * 1024 * 128];          //  32 MB  V[b,h] = c_kv @ M-slice
__device__ float g_logits[64L * 1024 * 1024];    // 256 MB  logits -> P (in place)

// ---------------- helpers -------------------------------------------------------
__device__ __forceinline__ unsigned f2tf(float f) {
    unsigned u;
    asm("cvt.rna.tf32.f32 %0, %1;" : "=r"(u) : "f"(f));
    return u;
}
__device__ __forceinline__ float f2tff(float f) { return __uint_as_float(f2tf(f)); }

__device__ __forceinline__ void mma_tf32(float* c, const unsigned* a, const unsigned* b) {
    asm volatile(
        "mma.sync.aligned.m16n8k8.row.col.f32.tf32.tf32.f32 "
        "{%0,%1,%2,%3}, {%4,%5,%6,%7}, {%8,%9}, {%0,%1,%2,%3};"
        : "+f"(c[0]), "+f"(c[1]), "+f"(c[2]), "+f"(c[3])
        : "r"(a[0]), "r"(a[1]), "r"(a[2]), "r"(a[3]), "r"(b[0]), "r"(b[1]));
}

#define CP16(dst, src) \
    asm volatile("cp.async.cg.shared.global [%0], [%1], 16;" :: "r"(dst), "l"(src))
#define CP_COMMIT() asm volatile("cp.async.commit_group;")
#define CP_WAIT1()  asm volatile("cp.async.wait_group 1;")

// ---------------- tf32 GEMM: cp.async 3-stage, 512 threads (R4 config) ----------
// Block tile 256(M) x 128(N) x 32(K). 16 warps as 4(m) x 4(n), warp tile 64x32.
// Smem layouts (words):
//   TA=0: As[m][k]  stride 36   TA=1: As[k][m]  stride 264
//   TB=1: Bs[n][k]  stride 36   TB=0: Bs[k][n]  stride 136
// MODE: 0 plain, 1 causal tile-skip, 2 causal K-limit. ROUND: tf32-round output.
#define ASZW 9216
#define BSZW 4608
#define STAGEW (ASZW + BSZW)
#define SMEM_BYTES (3 * STAGEW * 4)  // 165888 B

template <bool TA, bool TB, int MODE, bool ROUND>
__global__ void __launch_bounds__(512, 1) gemm_tc3(
        const float* __restrict__ A, const float* __restrict__ B,
        float* __restrict__ C, int M, int N, int K,
        int lda, int ldb, int ldc,
        long long sAq, long long sAr, long long sBq, long long sBr,
        long long sCq, long long sCr, int zdiv) {
    const int m0 = blockIdx.y * 256;
    const int n0 = blockIdx.x * 128;
    if (MODE == 1 && n0 >= m0 + 256) return;

    int z = blockIdx.z;
    int zq = z / zdiv, zr = z % zdiv;
    A += (long long)zq * sAq + (long long)zr * sAr;
    B += (long long)zq * sBq + (long long)zr * sBr;
    C += (long long)zq * sCq + (long long)zr * sCr;

    const int Keff = (MODE == 2) ? ((m0 + 256 < K) ? m0 + 256 : K) : K;
    const int ntiles = Keff >> 5;

    extern __shared__ float sh[];
    const unsigned shb = (unsigned)__cvta_generic_to_shared(sh);

    const int tid  = threadIdx.x;
    const int lane = tid & 31;
    const int warp = tid >> 5;
    const int wm = (warp >> 2) * 64;
    const int wn = (warp & 3) * 32;
    const int lane4 = lane & 3;
    const int laneg = lane >> 2;

    float acc[4][4][4] = {};

    auto issue = [&](int t) {
        const int k0 = t << 5;
        const unsigned As = shb + (t % 3) * (STAGEW * 4);
        const unsigned Bs = As + ASZW * 4;
        if (!TA) {
            const int row = tid >> 1;
            const float* src = A + (long long)(m0 + row) * lda + k0 + (tid & 1) * 16;
            const unsigned dst = As + (row * 36 + (tid & 1) * 16) * 4;
#pragma unroll
            for (int i = 0; i < 4; i++) CP16(dst + i * 16, src + i * 4);
        } else {
            const int k = tid >> 4, f4 = (tid & 15) * 4;
            const float* src = A + (long long)(k0 + k) * lda + m0 + f4 * 4;
            const unsigned dst = As + (k * 264 + f4 * 4) * 4;
#pragma unroll
            for (int i = 0; i < 4; i++) CP16(dst + i * 16, src + i * 4);
        }
        if (TB) {
            const int n = tid >> 2, f4 = (tid & 3) * 2;
            const float* src = B + (long long)(n0 + n) * ldb + k0 + f4 * 4;
            const unsigned dst = Bs + (n * 36 + f4 * 4) * 4;
#pragma unroll
            for (int i = 0; i < 2; i++) CP16(dst + i * 16, src + i * 4);
        } else {
            const int k = tid >> 4, f4 = (tid & 15) * 2;
            const float* src = B + (long long)(k0 + k) * ldb + n0 + f4 * 4;
            const unsigned dst = Bs + (k * 136 + f4 * 4) * 4;
#pragma unroll
            for (int i = 0; i < 2; i++) CP16(dst + i * 16, src + i * 4);
        }
        CP_COMMIT();
    };

    issue(0);
    if (ntiles > 1) issue(1);

    for (int t = 0; t < ntiles; t++) {
        CP_WAIT1();
        __syncthreads();
        if (t + 2 < ntiles) issue(t + 2);

        const unsigned* As = (const unsigned*)sh + (t % 3) * STAGEW;
        const unsigned* Bs = As + ASZW;

#pragma unroll
        for (int kk = 0; kk < 32; kk += 8) {
            const int k1 = kk + lane4, k2 = k1 + 4;
            unsigned a[4][4], b[4][2];
#pragma unroll
            for (int mi = 0; mi < 4; mi++) {
                const int mr = wm + mi * 16 + laneg;
                if (!TA) {
                    a[mi][0] = As[mr * 36 + k1];
                    a[mi][1] = As[(mr + 8) * 36 + k1];
                    a[mi][2] = As[mr * 36 + k2];
                    a[mi][3] = As[(mr + 8) * 36 + k2];
                } else {
                    a[mi][0] = As[k1 * 264 + mr];
                    a[mi][1] = As[k1 * 264 + mr + 8];
                    a[mi][2] = As[k2 * 264 + mr];
                    a[mi][3] = As[k2 * 264 + mr + 8];
                }
            }
#pragma unroll
            for (int ni = 0; ni < 4; ni++) {
                const int nc = wn + ni * 8 + laneg;
                if (TB) {
                    b[ni][0] = Bs[nc * 36 + k1];
                    b[ni][1] = Bs[nc * 36 + k2];
                } else {
                    b[ni][0] = Bs[k1 * 136 + nc];
                    b[ni][1] = Bs[k2 * 136 + nc];
                }
            }
#pragma unroll
            for (int mi = 0; mi < 4; mi++)
#pragma unroll
                for (int ni = 0; ni < 4; ni++)
                    mma_tf32(acc[mi][ni], a[mi], b[ni]);
        }
        __syncthreads();
    }

#pragma unroll
    for (int mi = 0; mi < 4; mi++) {
#pragma unroll
        for (int ni = 0; ni < 4; ni++) {
            const int row = m0 + wm + mi * 16 + laneg;
            const int col = n0 + wn + ni * 8 + lane4 * 2;
            float v0 = acc[mi][ni][0], v1 = acc[mi][ni][1];
            float v2 = acc[mi][ni][2], v3 = acc[mi][ni][3];
            if (ROUND) { v0 = f2tff(v0); v1 = f2tff(v1); v2 = f2tff(v2); v3 = f2tff(v3); }
            *reinterpret_cast<float2*>(&C[(long long)row * ldc + col]) = make_float2(v0, v1);
            *reinterpret_cast<float2*>(&C[(long long)(row + 8) * ldc + col]) = make_float2(v2, v3);
        }
    }
}

// ---------------- tf32 round-copy ----------------------------------------------
__global__ void round_copy(const float* __restrict__ in, float* __restrict__ out, int n4) {
    int idx = blockIdx.x * blockDim.x + threadIdx.x;
    if (idx >= n4) return;
    float4 v = reinterpret_cast<const float4*>(in)[idx];
    v.x = f2tff(v.x); v.y = f2tff(v.y); v.z = f2tff(v.z); v.w = f2tff(v.w);
    reinterpret_cast<float4*>(out)[idx] = v;
}

// ---------------- weight concat: Wcat = [W_dq ; W_kr ; pad] (rounded) -----------
__global__ void build_wcat(const float* __restrict__ Wdq,
                           const float* __restrict__ Wkr,
                           float* __restrict__ Wcat) {
    int idx = blockIdx.x * blockDim.x + threadIdx.x;
    if (idx >= 576 * 512) return;
    int row = idx >> 9, c4 = idx & 511;
    float4 v = (row < 512)
        ? reinterpret_cast<const float4*>(Wdq)[row * 512 + c4]
        : reinterpret_cast<const float4*>(Wkr)[(row - 512) * 512 + c4];
    v.x = f2tff(v.x); v.y = f2tff(v.y); v.z = f2tff(v.z); v.w = f2tff(v.w);
    reinterpret_cast<float4*>(Wcat)[row * 512 + c4] = v;
}

// ---------------- rope ----------------------------------------------------------
__global__ void rope_q_kernel(const float* __restrict__ cqr,
                              const float* __restrict__ fc,
                              const float* __restrict__ fs,
                              float* __restrict__ qcat) {
    int idx = blockIdx.x * blockDim.x + threadIdx.x;
    if (idx >= 4 * 1024 * 16 * 32) return;
    int j = idx & 31;
    int h = (idx >> 5) & 15;
    int t = (idx >> 9) & 1023;
    int b = idx >> 19;
    long long src = (((long long)(b * 1024 + t)) * 1024) + h * 64 + 2 * j;
    float re = cqr[src], im = cqr[src + 1];
    float c = fc[t * 32 + j], s = fs[t * 32 + j];
    long long dst = (((long long)(b * 16 + h)) * 1024 + t) * 576 + 512 + 2 * j;
    qcat[dst]     = f2tff(re * c - im * s);
    qcat[dst + 1] = f2tff(re * s + im * c);
}

__global__ void rope_k_kernel(const float* __restrict__ cqx,
                              const float* __restrict__ fc,
                              const float* __restrict__ fs,
                              float* __restrict__ kcat) {
    int idx = blockIdx.x * blockDim.x + threadIdx.x;
    if (idx >= 4 * 1024 * 32) return;
    int j = idx & 31;
    int t = (idx >> 5) & 1023;
    int b = idx >> 15;
    long long src = ((long long)(b * 1024 + t)) * 640 + 512 + 2 * j;
    float re = cqx[src], im = cqx[src + 1];
    float c = fc[t * 32 + j], s = fs[t * 32 + j];
    long long dst = ((long long)(b * 1024 + t)) * 576 + 512 + 2 * j;
    kcat[dst]     = f2tff(re * c - im * s);
    kcat[dst + 1] = f2tff(re * s + im * c);
}

// ---------------- single-pass softmax (smem-staged, in place) -------------------
__global__ void __launch_bounds__(256) softmax_kernel(float* __restrict__ L) {
    const int r = blockIdx.x;           // (b*NH + h)*T + t
    const int t = r & 1023;
    float* row = L + (long long)r * 1024;
    const float scale = 0.07216878364870323f;
    const int tid = threadIdx.x;        // 256
    const int lane = tid & 31, wid = tid >> 5;
    __shared__ float buf[1024];
    __shared__ float red[8];

    // pass 1: one gmem read; scale + mask into smem; running max
    float m = -INFINITY;
#pragma unroll
    for (int i = 0; i < 4; i++) {
        int s = tid + i * 256;
        float v = (s <= t) ? row[s] * scale : -INFINITY;
        buf[s] = v;
        m = fmaxf(m, v);
    }
#pragma unroll
    for (int o = 16; o; o >>= 1) m = fmaxf(m, __shfl_xor_sync(~0u, m, o));
    if (lane == 0) red[wid] = m;
    __syncthreads();
    m = red[0];
#pragma unroll
    for (int w = 1; w < 8; w++) m = fmaxf(m, red[w]);

    // pass 2: exp into smem; running sum
    float sum = 0.0f;
#pragma unroll
    for (int i = 0; i < 4; i++) {
        int s = tid + i * 256;
        float e = __expf(buf[s] - m);   // exp(-inf) = 0 handles the mask
        buf[s] = e;
        sum += e;
    }
#pragma unroll
    for (int o = 16; o; o >>= 1) sum += __shfl_xor_sync(~0u, sum, o);
    if (lane == 0) red[wid] = sum;
    __syncthreads();
    sum = red[0];
#pragma unroll
    for (int w = 1; w < 8; w++) sum += red[w];
    const float inv = 1.0f / sum;

    // pass 3: one gmem write (tf32-rounded P)
#pragma unroll
    for (int i = 0; i < 4; i++) {
        int s = tid + i * 256;
        row[s] = f2tff(buf[s] * inv);
    }
}

// ---------------- launcher -------------------------------------------------------
extern "C" void kernel_launch(void* const* d_in, const int* in_sizes, int n_in,
                              void* d_out, int out_size) {
    (void)in_sizes; (void)n_in; (void)out_size;
    const float* x     = (const float*)d_in[0];
    const float* W_dq  = (const float*)d_in[1];
    const float* W_uq  = (const float*)d_in[2];
    const float* W_dkv = (const float*)d_in[3];
    const float* W_uk  = (const float*)d_in[4];
    const float* W_uv  = (const float*)d_in[5];
    const float* W_o   = (const float*)d_in[6];
    const float* W_qr  = (const float*)d_in[7];
    const float* W_kr  = (const float*)d_in[8];
    const float* fc    = (const float*)d_in[9];
    const float* fs    = (const float*)d_in[10];
    float* out = (float*)d_out;

    float *keff, *Mm, *wcat, *xr, *wdkv, *wqr, *wuq, *wuk, *wuv, *wo;
    float *cqx, *cqr, *qcat, *kcat, *vv, *logits;
    cudaGetSymbolAddress((void**)&keff,   g_keff);
    cudaGetSymbolAddress((void**)&Mm,     g_M);
    cudaGetSymbolAddress((void**)&wcat,   g_wcat);
    cudaGetSymbolAddress((void**)&xr,     g_xr);
    cudaGetSymbolAddress((void**)&wdkv,   g_wdkv);
    cudaGetSymbolAddress((void**)&wqr,    g_wqr);
    cudaGetSymbolAddress((void**)&wuq,    g_wuq);
    cudaGetSymbolAddress((void**)&wuk,    g_wuk);
    cudaGetSymbolAddress((void**)&wuv,    g_wuv);
    cudaGetSymbolAddress((void**)&wo,     g_wo);
    cudaGetSymbolAddress((void**)&cqx,    g_cqx);
    cudaGetSymbolAddress((void**)&cqr,    g_cqr);
    cudaGetSymbolAddress((void**)&qcat,   g_qcat);
    cudaGetSymbolAddress((void**)&kcat,   g_kcat);
    cudaGetSymbolAddress((void**)&vv,     g_v);
    cudaGetSymbolAddress((void**)&logits, g_logits);

    cudaFuncSetAttribute(gemm_tc3<false, true,  0, true >, cudaFuncAttributeMaxDynamicSharedMemorySize, SMEM_BYTES);
    cudaFuncSetAttribute(gemm_tc3<false, false, 0, true >, cudaFuncAttributeMaxDynamicSharedMemorySize, SMEM_BYTES);
    cudaFuncSetAttribute(gemm_tc3<true,  true,  0, true >, cudaFuncAttributeMaxDynamicSharedMemorySize, SMEM_BYTES);
    cudaFuncSetAttribute(gemm_tc3<false, true,  0, false>, cudaFuncAttributeMaxDynamicSharedMemorySize, SMEM_BYTES);
    cudaFuncSetAttribute(gemm_tc3<false, true,  1, false>, cudaFuncAttributeMaxDynamicSharedMemorySize, SMEM_BYTES);
    cudaFuncSetAttribute(gemm_tc3<false, false, 2, false>, cudaFuncAttributeMaxDynamicSharedMemorySize, SMEM_BYTES);

    dim3 blk(512);
    const long long QZ = 1024LL * 576;
    const long long KZ = 1024LL * 576;
    const long long LZ = 1024LL * 1024;
    const long long VZ = 1024LL * 128;

    // --- pre-round operands to tf32 ---
    round_copy<<<(2097152 + 255) / 256, 256>>>(x,     xr,   2097152);
    round_copy<<<(262144  + 255) / 256, 256>>>(W_dkv, wdkv, 262144);
    round_copy<<<(131072  + 255) / 256, 256>>>(W_qr,  wqr,  131072);
    round_copy<<<(262144  + 255) / 256, 256>>>(W_uq,  wuq,  262144);
    round_copy<<<(262144  + 255) / 256, 256>>>(W_uk,  wuk,  262144);
    round_copy<<<(262144  + 255) / 256, 256>>>(W_uv,  wuv,  262144);
    round_copy<<<(1048576 + 255) / 256, 256>>>(W_o,   wo,   1048576);
    build_wcat<<<(576 * 512 + 255) / 256, 256>>>(W_dq, W_kr, wcat);

    // 1) cqx (4096x640) = x @ Wcat^T
    gemm_tc3<false, true, 0, true><<<dim3(5, 16, 1), blk, SMEM_BYTES>>>(
        xr, wcat, cqx, 4096, 640, 2048, 2048, 2048, 640,
        0, 0, 0, 0, 0, 0, 1);

    // 2) kcat[:, 0:512] = x @ W_dkv^T
    gemm_tc3<false, true, 0, true><<<dim3(4, 16, 1), blk, SMEM_BYTES>>>(
        xr, wdkv, kcat, 4096, 512, 2048, 2048, 2048, 576,
        0, 0, 0, 0, 0, 0, 1);

    // 3) k_eff[h] = Wuq_slice @ Wuk_slice
    gemm_tc3<false, false, 0, true><<<dim3(4, 2, 16), blk, SMEM_BYTES>>>(
        wuq, wuk, keff, 512, 512, 128, 2048, 512, 512,
        128, 0, 128LL * 512, 0, 512LL * 512, 0, 1);

    // 4) M = W_uv^T @ W_o^T
    gemm_tc3<true, true, 0, true><<<dim3(16, 2, 1), blk, SMEM_BYTES>>>(
        wuv, wo, Mm, 512, 2048, 2048, 512, 2048, 2048,
        0, 0, 0, 0, 0, 0, 1);

    // 5) c_qr = c_q @ W_qr^T
    gemm_tc3<false, true, 0, false><<<dim3(8, 16, 1), blk, SMEM_BYTES>>>(
        cqx, wqr, cqr, 4096, 1024, 512, 640, 512, 1024,
        0, 0, 0, 0, 0, 0, 1);

    // 6) rope into concat tails
    rope_q_kernel<<<8192, 256>>>(cqr, fc, fs, qcat);
    rope_k_kernel<<<512, 256>>>(cqx, fc, fs, kcat);

    // 7) q_abs -> qcat[:, 0:512] = c_q[b] @ k_eff[h]
    gemm_tc3<false, false, 0, true><<<dim3(4, 4, 64), blk, SMEM_BYTES>>>(
        cqx, keff, qcat, 1024, 512, 512, 640, 512, 576,
        1024LL * 640, 0, 0, 512LL * 512,
        16LL * QZ, QZ, 16);

    // 8) V[b,h] (1024x128) = c_kv[b] @ M[:, h*128:(h+1)*128]   (z = b*16+h)
    gemm_tc3<false, false, 0, true><<<dim3(1, 4, 64), blk, SMEM_BYTES>>>(
        kcat, Mm, vv, 1024, 128, 512, 576, 2048, 128,
        KZ, 0, 0, 128,
        16LL * VZ, VZ, 16);

    // 9) logits = qcat @ kcat^T (K=576), causal tile-skip
    gemm_tc3<false, true, 1, false><<<dim3(8, 4, 64), blk, SMEM_BYTES>>>(
        qcat, kcat, logits, 1024, 1024, 576, 576, 576, 1024,
        16LL * QZ, QZ, KZ, 0,
        16LL * LZ, LZ, 16);

    // 10) softmax (single-pass, smem-staged)
    softmax_kernel<<<65536, 256>>>(logits);

    // 11) out[b, :, h*128:(h+1)*128] = P[b,h] @ V[b,h], causal K-limit
    gemm_tc3<false, false, 2, false><<<dim3(1, 4, 64), blk, SMEM_BYTES>>>(
        logits, vv, out, 1024, 128, 1024, 1024, 128, 2048,
        16LL * LZ, LZ, 16LL * VZ, VZ,
        1024LL * 2048, 128, 16);
}

// round 7
// speedup vs baseline: 1.6860x; 1.3218x over previous
#include <cuda_runtime.h>
#include <math.h>

// B=4, T=1024, C=2048, NH=16, HS=128, NLQ=512, NLKV=512, DHR=64
// scale = 1/sqrt(192)

// ---------------- scratch (device globals) ------------------------------------
__device__ float g_M[512L * 2048];               //   4 MB  M = W_uv^T @ W_o^T
__device__ float g_wcat[640L * 2048];            //   5 MB  [W_dq ; W_kr ; pad]
__device__ float g_xr[4096L * 2048];             //  32 MB  x rounded to tf32
__device__ float g_wdkv[512L * 2048];            //   4 MB
__device__ float g_wqr[1024L * 512];             //   2 MB
__device__ float g_wuq[2048L * 512];             //   4 MB
__device__ float g_wuk[2048L * 512];             //   4 MB
__device__ float g_wuv[2048L * 512];             //   4 MB
__device__ float g_wo[2048L * 2048];             //  16 MB
__device__ float g_cqx[4096L * 640];             //  10 MB  [c_q | c_kr | pad]
__device__ float g_cqr[4096L * 1024];            //  16 MB  c_qr (pre-rope)
__device__ float g_qh[64L * 1024 * 192];         //  50 MB  per-head [q_c | q_r]
__device__ float g_kh[64L * 1024 * 192];         //  50 MB  per-head [k_c | k_r]
__device__ float g_kcat[4096L * 576];            // 9.4 MB  [c_kv | pad]
__device__ float g_v[64L * 1024 * 128];          //  32 MB  V[b,h] = c_kv @ M-slice
__device__ float g_logits[64L * 1024 * 1024];    // 256 MB  logits -> P (in place)

// ---------------- helpers -------------------------------------------------------
__device__ __forceinline__ unsigned f2tf(float f) {
    unsigned u;
    asm("cvt.rna.tf32.f32 %0, %1;" : "=r"(u) : "f"(f));
    return u;
}
__device__ __forceinline__ float f2tff(float f) { return __uint_as_float(f2tf(f)); }

__device__ __forceinline__ void mma_tf32(float* c, const unsigned* a, const unsigned* b) {
    asm volatile(
        "mma.sync.aligned.m16n8k8.row.col.f32.tf32.tf32.f32 "
        "{%0,%1,%2,%3}, {%4,%5,%6,%7}, {%8,%9}, {%0,%1,%2,%3};"
        : "+f"(c[0]), "+f"(c[1]), "+f"(c[2]), "+f"(c[3])
        : "r"(a[0]), "r"(a[1]), "r"(a[2]), "r"(a[3]), "r"(b[0]), "r"(b[1]));
}

#define CP16(dst, src) \
    asm volatile("cp.async.cg.shared.global [%0], [%1], 16;" :: "r"(dst), "l"(src))
#define CP_COMMIT() asm volatile("cp.async.commit_group;")
#define CP_WAIT1()  asm volatile("cp.async.wait_group 1;")

// ---------------- tf32 GEMM: cp.async 3-stage, 512 threads ----------------------
// Block tile 256(M) x 128(N) x 32(K). 16 warps as 4(m) x 4(n), warp tile 64x32.
// MODE: 0 plain, 1 causal tile-skip, 2 causal K-limit.
// ROUND: tf32-round the output.
// HEADC: head-sliced C: C += blockIdx.x * sHC, column index local to the N-tile.
#define ASZW 9216
#define BSZW 4608
#define STAGEW (ASZW + BSZW)
#define SMEM_BYTES (3 * STAGEW * 4)  // 165888 B

template <bool TA, bool TB, int MODE, bool ROUND, bool HEADC>
__global__ void __launch_bounds__(512, 1) gemm_tc3(
        const float* __restrict__ A, const float* __restrict__ B,
        float* __restrict__ C, int M, int N, int K,
        int lda, int ldb, int ldc,
        long long sAq, long long sAr, long long sBq, long long sBr,
        long long sCq, long long sCr, int zdiv, long long sHC) {
    const int m0 = blockIdx.y * 256;
    const int n0 = blockIdx.x * 128;
    if (MODE == 1 && n0 >= m0 + 256) return;

    int z = blockIdx.z;
    int zq = z / zdiv, zr = z % zdiv;
    A += (long long)zq * sAq + (long long)zr * sAr;
    B += (long long)zq * sBq + (long long)zr * sBr;
    C += (long long)zq * sCq + (long long)zr * sCr;
    if (HEADC) C += (long long)blockIdx.x * sHC;

    const int Keff = (MODE == 2) ? ((m0 + 256 < K) ? m0 + 256 : K) : K;
    const int ntiles = Keff >> 5;

    extern __shared__ float sh[];
    const unsigned shb = (unsigned)__cvta_generic_to_shared(sh);

    const int tid  = threadIdx.x;
    const int lane = tid & 31;
    const int warp = tid >> 5;
    const int wm = (warp >> 2) * 64;
    const int wn = (warp & 3) * 32;
    const int lane4 = lane & 3;
    const int laneg = lane >> 2;

    float acc[4][4][4] = {};

    auto issue = [&](int t) {
        const int k0 = t << 5;
        const unsigned As = shb + (t % 3) * (STAGEW * 4);
        const unsigned Bs = As + ASZW * 4;
        if (!TA) {
            const int row = tid >> 1;
            const float* src = A + (long long)(m0 + row) * lda + k0 + (tid & 1) * 16;
            const unsigned dst = As + (row * 36 + (tid & 1) * 16) * 4;
#pragma unroll
            for (int i = 0; i < 4; i++) CP16(dst + i * 16, src + i * 4);
        } else {
            const int k = tid >> 4, f4 = (tid & 15) * 4;
            const float* src = A + (long long)(k0 + k) * lda + m0 + f4 * 4;
            const unsigned dst = As + (k * 264 + f4 * 4) * 4;
#pragma unroll
            for (int i = 0; i < 4; i++) CP16(dst + i * 16, src + i * 4);
        }
        if (TB) {
            const int n = tid >> 2, f4 = (tid & 3) * 2;
            const float* src = B + (long long)(n0 + n) * ldb + k0 + f4 * 4;
            const unsigned dst = Bs + (n * 36 + f4 * 4) * 4;
#pragma unroll
            for (int i = 0; i < 2; i++) CP16(dst + i * 16, src + i * 4);
        } else {
            const int k = tid >> 4, f4 = (tid & 15) * 2;
            const float* src = B + (long long)(k0 + k) * ldb + n0 + f4 * 4;
            const unsigned dst = Bs + (k * 136 + f4 * 4) * 4;
#pragma unroll
            for (int i = 0; i < 2; i++) CP16(dst + i * 16, src + i * 4);
        }
        CP_COMMIT();
    };

    issue(0);
    if (ntiles > 1) issue(1);

    for (int t = 0; t < ntiles; t++) {
        CP_WAIT1();
        __syncthreads();
        if (t + 2 < ntiles) issue(t + 2);

        const unsigned* As = (const unsigned*)sh + (t % 3) * STAGEW;
        const unsigned* Bs = As + ASZW;

#pragma unroll
        for (int kk = 0; kk < 32; kk += 8) {
            const int k1 = kk + lane4, k2 = k1 + 4;
            unsigned a[4][4], b[4][2];
#pragma unroll
            for (int mi = 0; mi < 4; mi++) {
                const int mr = wm + mi * 16 + laneg;
                if (!TA) {
                    a[mi][0] = As[mr * 36 + k1];
                    a[mi][1] = As[(mr + 8) * 36 + k1];
                    a[mi][2] = As[mr * 36 + k2];
                    a[mi][3] = As[(mr + 8) * 36 + k2];
                } else {
                    a[mi][0] = As[k1 * 264 + mr];
                    a[mi][1] = As[k1 * 264 + mr + 8];
                    a[mi][2] = As[k2 * 264 + mr];
                    a[mi][3] = As[k2 * 264 + mr + 8];
                }
            }
#pragma unroll
            for (int ni = 0; ni < 4; ni++) {
                const int nc = wn + ni * 8 + laneg;
                if (TB) {
                    b[ni][0] = Bs[nc * 36 + k1];
                    b[ni][1] = Bs[nc * 36 + k2];
                } else {
                    b[ni][0] = Bs[k1 * 136 + nc];
                    b[ni][1] = Bs[k2 * 136 + nc];
                }
            }
#pragma unroll
            for (int mi = 0; mi < 4; mi++)
#pragma unroll
                for (int ni = 0; ni < 4; ni++)
                    mma_tf32(acc[mi][ni], a[mi], b[ni]);
        }
        __syncthreads();
    }

#pragma unroll
    for (int mi = 0; mi < 4; mi++) {
#pragma unroll
        for (int ni = 0; ni < 4; ni++) {
            const int row = m0 + wm + mi * 16 + laneg;
            const int col = (HEADC ? 0 : n0) + wn + ni * 8 + lane4 * 2;
            float v0 = acc[mi][ni][0], v1 = acc[mi][ni][1];
            float v2 = acc[mi][ni][2], v3 = acc[mi][ni][3];
            if (ROUND) { v0 = f2tff(v0); v1 = f2tff(v1); v2 = f2tff(v2); v3 = f2tff(v3); }
            *reinterpret_cast<float2*>(&C[(long long)row * ldc + col]) = make_float2(v0, v1);
            *reinterpret_cast<float2*>(&C[(long long)(row + 8) * ldc + col]) = make_float2(v2, v3);
        }
    }
}

// ---------------- tf32 round-copy ----------------------------------------------
__global__ void round_copy(const float* __restrict__ in, float* __restrict__ out, int n4) {
    int idx = blockIdx.x * blockDim.x + threadIdx.x;
    if (idx >= n4) return;
    float4 v = reinterpret_cast<const float4*>(in)[idx];
    v.x = f2tff(v.x); v.y = f2tff(v.y); v.z = f2tff(v.z); v.w = f2tff(v.w);
    reinterpret_cast<float4*>(out)[idx] = v;
}

// ---------------- weight concat: Wcat = [W_dq ; W_kr ; pad] (rounded) -----------
__global__ void build_wcat(const float* __restrict__ Wdq,
                           const float* __restrict__ Wkr,
                           float* __restrict__ Wcat) {
    int idx = blockIdx.x * blockDim.x + threadIdx.x;
    if (idx >= 576 * 512) return;
    int row = idx >> 9, c4 = idx & 511;
    float4 v = (row < 512)
        ? reinterpret_cast<const float4*>(Wdq)[row * 512 + c4]
        : reinterpret_cast<const float4*>(Wkr)[(row - 512) * 512 + c4];
    v.x = f2tff(v.x); v.y = f2tff(v.y); v.z = f2tff(v.z); v.w = f2tff(v.w);
    reinterpret_cast<float4*>(Wcat)[row * 512 + c4] = v;
}

// ---------------- rope ----------------------------------------------------------
__global__ void rope_q_kernel(const float* __restrict__ cqr,
                              const float* __restrict__ fc,
                              const float* __restrict__ fs,
                              float* __restrict__ qh) {
    int idx = blockIdx.x * blockDim.x + threadIdx.x;  // B*T*NH*32
    if (idx >= 4 * 1024 * 16 * 32) return;
    int j = idx & 31;
    int h = (idx >> 5) & 15;
    int t = (idx >> 9) & 1023;
    int b = idx >> 19;
    long long src = (((long long)(b * 1024 + t)) * 1024) + h * 64 + 2 * j;
    float re = cqr[src], im = cqr[src + 1];
    float c = fc[t * 32 + j], s = fs[t * 32 + j];
    long long dst = (((long long)(b * 16 + h)) * 1024 + t) * 192 + 128 + 2 * j;
    qh[dst]     = f2tff(re * c - im * s);
    qh[dst + 1] = f2tff(re * s + im * c);
}

__global__ void rope_k_kernel(const float* __restrict__ cqx,
                              const float* __restrict__ fc,
                              const float* __restrict__ fs,
                              float* __restrict__ kh) {
    int idx = blockIdx.x * blockDim.x + threadIdx.x;  // B*T*32
    if (idx >= 4 * 1024 * 32) return;
    int j = idx & 31;
    int t = (idx >> 5) & 1023;
    int b = idx >> 15;
    long long src = ((long long)(b * 1024 + t)) * 640 + 512 + 2 * j;
    float re = cqx[src], im = cqx[src + 1];
    float c = fc[t * 32 + j], s = fs[t * 32 + j];
    float o0 = f2tff(re * c - im * s);
    float o1 = f2tff(re * s + im * c);
#pragma unroll
    for (int h = 0; h < 16; h++) {   // k_r is broadcast across heads
        long long dst = (((long long)(b * 16 + h)) * 1024 + t) * 192 + 128 + 2 * j;
        kh[dst]     = o0;
        kh[dst + 1] = o1;
    }
}

// ---------------- single-pass softmax (smem-staged, in place) -------------------
__global__ void __launch_bounds__(256) softmax_kernel(float* __restrict__ L) {
    const int r = blockIdx.x;           // (b*NH + h)*T + t
    const int t = r & 1023;
    float* row = L + (long long)r * 1024;
    const float scale = 0.07216878364870323f;
    const int tid = threadIdx.x;        // 256
    const int lane = tid & 31, wid = tid >> 5;
    __shared__ float buf[1024];
    __shared__ float red[8];

    float m = -INFINITY;
#pragma unroll
    for (int i = 0; i < 4; i++) {
        int s = tid + i * 256;
        float v = (s <= t) ? row[s] * scale : -INFINITY;
        buf[s] = v;
        m = fmaxf(m, v);
    }
#pragma unroll
    for (int o = 16; o; o >>= 1) m = fmaxf(m, __shfl_xor_sync(~0u, m, o));
    if (lane == 0) red[wid] = m;
    __syncthreads();
    m = red[0];
#pragma unroll
    for (int w = 1; w < 8; w++) m = fmaxf(m, red[w]);

    float sum = 0.0f;
#pragma unroll
    for (int i = 0; i < 4; i++) {
        int s = tid + i * 256;
        float e = __expf(buf[s] - m);
        buf[s] = e;
        sum += e;
    }
#pragma unroll
    for (int o = 16; o; o >>= 1) sum += __shfl_xor_sync(~0u, sum, o);
    if (lane == 0) red[wid] = sum;
    __syncthreads();
    sum = red[0];
#pragma unroll
    for (int w = 1; w < 8; w++) sum += red[w];
    const float inv = 1.0f / sum;

#pragma unroll
    for (int i = 0; i < 4; i++) {
        int s = tid + i * 256;
        row[s] = f2tff(buf[s] * inv);
    }
}

// ---------------- launcher -------------------------------------------------------
extern "C" void kernel_launch(void* const* d_in, const int* in_sizes, int n_in,
                              void* d_out, int out_size) {
    (void)in_sizes; (void)n_in; (void)out_size;
    const float* x     = (const float*)d_in[0];
    const float* W_dq  = (const float*)d_in[1];
    const float* W_uq  = (const float*)d_in[2];
    const float* W_dkv = (const float*)d_in[3];
    const float* W_uk  = (const float*)d_in[4];
    const float* W_uv  = (const float*)d_in[5];
    const float* W_o   = (const float*)d_in[6];
    const float* W_qr  = (const float*)d_in[7];
    const float* W_kr  = (const float*)d_in[8];
    const float* fc    = (const float*)d_in[9];
    const float* fs    = (const float*)d_in[10];
    float* out = (float*)d_out;

    float *Mm, *wcat, *xr, *wdkv, *wqr, *wuq, *wuk, *wuv, *wo;
    float *cqx, *cqr, *qh, *kh, *kcat, *vv, *logits;
    cudaGetSymbolAddress((void**)&Mm,     g_M);
    cudaGetSymbolAddress((void**)&wcat,   g_wcat);
    cudaGetSymbolAddress((void**)&xr,     g_xr);
    cudaGetSymbolAddress((void**)&wdkv,   g_wdkv);
    cudaGetSymbolAddress((void**)&wqr,    g_wqr);
    cudaGetSymbolAddress((void**)&wuq,    g_wuq);
    cudaGetSymbolAddress((void**)&wuk,    g_wuk);
    cudaGetSymbolAddress((void**)&wuv,    g_wuv);
    cudaGetSymbolAddress((void**)&wo,     g_wo);
    cudaGetSymbolAddress((void**)&cqx,    g_cqx);
    cudaGetSymbolAddress((void**)&cqr,    g_cqr);
    cudaGetSymbolAddress((void**)&qh,     g_qh);
    cudaGetSymbolAddress((void**)&kh,     g_kh);
    cudaGetSymbolAddress((void**)&kcat,   g_kcat);
    cudaGetSymbolAddress((void**)&vv,     g_v);
    cudaGetSymbolAddress((void**)&logits, g_logits);

    cudaFuncSetAttribute(gemm_tc3<false, true,  0, true,  false>, cudaFuncAttributeMaxDynamicSharedMemorySize, SMEM_BYTES);
    cudaFuncSetAttribute(gemm_tc3<true,  true,  0, true,  false>, cudaFuncAttributeMaxDynamicSharedMemorySize, SMEM_BYTES);
    cudaFuncSetAttribute(gemm_tc3<false, true,  0, false, false>, cudaFuncAttributeMaxDynamicSharedMemorySize, SMEM_BYTES);
    cudaFuncSetAttribute(gemm_tc3<false, false, 0, true,  true >, cudaFuncAttributeMaxDynamicSharedMemorySize, SMEM_BYTES);
    cudaFuncSetAttribute(gemm_tc3<false, true,  0, true,  true >, cudaFuncAttributeMaxDynamicSharedMemorySize, SMEM_BYTES);
    cudaFuncSetAttribute(gemm_tc3<false, false, 0, true,  false>, cudaFuncAttributeMaxDynamicSharedMemorySize, SMEM_BYTES);
    cudaFuncSetAttribute(gemm_tc3<false, true,  1, false, false>, cudaFuncAttributeMaxDynamicSharedMemorySize, SMEM_BYTES);
    cudaFuncSetAttribute(gemm_tc3<false, false, 2, false, false>, cudaFuncAttributeMaxDynamicSharedMemorySize, SMEM_BYTES);

    dim3 blk(512);
    const long long HZ = 1024LL * 192;   // per-(b,h) stride in qh/kh
    const long long KZ = 1024LL * 576;   // per-b stride in kcat
    const long long LZ = 1024LL * 1024;
    const long long VZ = 1024LL * 128;

    // --- pre-round operands to tf32 ---
    round_copy<<<(2097152 + 255) / 256, 256>>>(x,     xr,   2097152);
    round_copy<<<(262144  + 255) / 256, 256>>>(W_dkv, wdkv, 262144);
    round_copy<<<(131072  + 255) / 256, 256>>>(W_qr,  wqr,  131072);
    round_copy<<<(262144  + 255) / 256, 256>>>(W_uq,  wuq,  262144);
    round_copy<<<(262144  + 255) / 256, 256>>>(W_uk,  wuk,  262144);
    round_copy<<<(262144  + 255) / 256, 256>>>(W_uv,  wuv,  262144);
    round_copy<<<(1048576 + 255) / 256, 256>>>(W_o,   wo,   1048576);
    build_wcat<<<(576 * 512 + 255) / 256, 256>>>(W_dq, W_kr, wcat);

    // 1) cqx (4096x640) = x @ Wcat^T
    gemm_tc3<false, true, 0, true, false><<<dim3(5, 16, 1), blk, SMEM_BYTES>>>(
        xr, wcat, cqx, 4096, 640, 2048, 2048, 2048, 640,
        0, 0, 0, 0, 0, 0, 1, 0);

    // 2) kcat[:, 0:512] = x @ W_dkv^T   (c_kv)
    gemm_tc3<false, true, 0, true, false><<<dim3(4, 16, 1), blk, SMEM_BYTES>>>(
        xr, wdkv, kcat, 4096, 512, 2048, 2048, 2048, 576,
        0, 0, 0, 0, 0, 0, 1, 0);

    // 3) M = W_uv^T @ W_o^T
    gemm_tc3<true, true, 0, true, false><<<dim3(16, 2, 1), blk, SMEM_BYTES>>>(
        wuv, wo, Mm, 512, 2048, 2048, 512, 2048, 2048,
        0, 0, 0, 0, 0, 0, 1, 0);

    // 4) c_qr = c_q @ W_qr^T
    gemm_tc3<false, true, 0, false, false><<<dim3(8, 16, 1), blk, SMEM_BYTES>>>(
        cqx, wqr, cqr, 4096, 1024, 512, 640, 512, 1024,
        0, 0, 0, 0, 0, 0, 1, 0);

    // 5) q per head -> qh[:, 0:128]: q = c_q[b] @ Wuq_view(512x2048), head-sliced C
    //    z = b (4), grid.x = 16 heads, grid.y = 4 (M=1024)
    gemm_tc3<false, false, 0, true, true><<<dim3(16, 4, 4), blk, SMEM_BYTES>>>(
        cqx, wuq, qh, 1024, 2048, 512, 640, 2048, 192,
        1024LL * 640, 0, 0, 0,
        16LL * HZ, 0, 1, HZ);

    // 6) k per head -> kh[:, 0:128]: k = c_kv[b] @ W_uk^T, head-sliced C
    gemm_tc3<false, true, 0, true, true><<<dim3(16, 4, 4), blk, SMEM_BYTES>>>(
        kcat, wuk, kh, 1024, 2048, 512, 576, 512, 192,
        KZ, 0, 0, 0,
        16LL * HZ, 0, 1, HZ);

    // 7) rope tails
    rope_q_kernel<<<8192, 256>>>(cqr, fc, fs, qh);
    rope_k_kernel<<<512, 256>>>(cqx, fc, fs, kh);

    // 8) V[b,h] (1024x128) = c_kv[b] @ M[:, h*128:(h+1)*128]
    gemm_tc3<false, false, 0, true, false><<<dim3(1, 4, 64), blk, SMEM_BYTES>>>(
        kcat, Mm, vv, 1024, 128, 512, 576, 2048, 128,
        KZ, 0, 0, 128,
        16LL * VZ, VZ, 16, 0);

    // 9) logits[b,h] = qh[b,h] @ kh[b,h]^T  (K=192), causal tile-skip
    gemm_tc3<false, true, 1, false, false><<<dim3(8, 4, 64), blk, SMEM_BYTES>>>(
        qh, kh, logits, 1024, 1024, 192, 192, 192, 1024,
        16LL * HZ, HZ, 16LL * HZ, HZ,
        16LL * LZ, LZ, 16, 0);

    // 10) softmax (single-pass)
    softmax_kernel<<<65536, 256>>>(logits);

    // 11) out[b, :, h*128:(h+1)*128] = P[b,h] @ V[b,h], causal K-limit
    gemm_tc3<false, false, 2, false, false><<<dim3(1, 4, 64), blk, SMEM_BYTES>>>(
        logits, vv, out, 1024, 128, 1024, 1024, 128, 2048,
        16LL * LZ, LZ, 16LL * VZ, VZ,
        1024LL * 2048, 128, 16, 0);
}